// round 4
// baseline (speedup 1.0000x reference)
#include <cuda_runtime.h>
#include <cstdint>

// Problem constants (match reference)
#define N_NODES   50000
#define N_EDGES   800000
#define N_TOT     850000      // edges + self loops
#define IN_CH     128
#define HID       256
#define N_GRAPHS  512
#define M_PAD     50048       // 391 * 128

// ---------------- scratch (device globals; no allocation allowed) -------------
__device__ float g_bufA[(size_t)M_PAD * IN_CH];   // aggregated input (layer 0)
__device__ float g_bufB[(size_t)M_PAD * HID];     // gemm outputs
__device__ float g_bufC[(size_t)M_PAD * HID];     // aggregated hidden
__device__ int   g_deg[N_NODES];
__device__ float g_dinv[N_NODES];
__device__ int   g_rowptr[N_NODES + 1];
__device__ int   g_cursor[N_NODES];
__device__ int   g_col[N_TOT];
__device__ float g_w[N_TOT];
__device__ int   g_gstart[N_GRAPHS + 1];

// ---------------- preprocessing ----------------------------------------------
__global__ void init_deg_kernel() {
    int i = blockIdx.x * blockDim.x + threadIdx.x;
    if (i < N_NODES) g_deg[i] = 1;   // self loop
}

__global__ void count_kernel(const int* __restrict__ dst) {
    int e = blockIdx.x * blockDim.x + threadIdx.x;
    if (e < N_EDGES) atomicAdd(&g_deg[dst[e]], 1);
}

__global__ void dinv_kernel() {
    int i = blockIdx.x * blockDim.x + threadIdx.x;
    if (i < N_NODES) g_dinv[i] = rsqrtf((float)g_deg[i]);
}

// single-block exclusive scan over g_deg -> g_rowptr / g_cursor
__global__ void scan_kernel() {
    __shared__ int sh[1024];
    __shared__ int carry_s;
    int tid = threadIdx.x;
    if (tid == 0) carry_s = 0;
    __syncthreads();
    for (int base = 0; base < N_NODES; base += 1024) {
        int i = base + tid;
        int v = (i < N_NODES) ? g_deg[i] : 0;
        sh[tid] = v;
        __syncthreads();
        #pragma unroll
        for (int off = 1; off < 1024; off <<= 1) {
            int t = (tid >= off) ? sh[tid - off] : 0;
            __syncthreads();
            sh[tid] += t;
            __syncthreads();
        }
        int excl = sh[tid] - v;
        int c = carry_s;
        if (i < N_NODES) { g_rowptr[i] = c + excl; g_cursor[i] = c + excl; }
        int total = sh[1023];
        __syncthreads();
        if (tid == 0) carry_s = c + total;
        __syncthreads();
    }
    if (tid == 0) g_rowptr[N_NODES] = carry_s;
}

__global__ void place_edges_kernel(const int* __restrict__ src,
                                   const int* __restrict__ dst) {
    int e = blockIdx.x * blockDim.x + threadIdx.x;
    if (e >= N_EDGES) return;
    int s = src[e], d = dst[e];
    int pos = atomicAdd(&g_cursor[d], 1);
    g_col[pos] = s;
    g_w[pos]   = g_dinv[s] * g_dinv[d];
}

__global__ void place_loops_kernel() {
    int v = blockIdx.x * blockDim.x + threadIdx.x;
    if (v >= N_NODES) return;
    int pos = atomicAdd(&g_cursor[v], 1);
    g_col[pos] = v;
    float dv = g_dinv[v];
    g_w[pos]  = dv * dv;
}

__global__ void zero_pads_kernel() {
    int i = blockIdx.x * blockDim.x + threadIdx.x;
    const int PAD = M_PAD - N_NODES;            // 48
    if (i < PAD * IN_CH) g_bufA[(size_t)N_NODES * IN_CH + i] = 0.f;
    if (i < PAD * HID) {
        g_bufB[(size_t)N_NODES * HID + i] = 0.f;
        g_bufC[(size_t)N_NODES * HID + i] = 0.f;
    }
}

// ---------------- aggregation: out[v] = sum_e w[e] * x[col[e]] ----------------
template <int C>
__global__ void __launch_bounds__(256)
aggregate_kernel(const float* __restrict__ x, float* __restrict__ out) {
    int warp = (blockIdx.x * blockDim.x + threadIdx.x) >> 5;
    int lane = threadIdx.x & 31;
    if (warp >= N_NODES) return;
    constexpr int V = C / 32;                   // floats per lane (4 or 8)
    float acc[V];
    #pragma unroll
    for (int q = 0; q < V; q++) acc[q] = 0.f;
    int s = g_rowptr[warp], e = g_rowptr[warp + 1];
    for (int i = s; i < e; i++) {
        int cidx = g_col[i];
        float wt = g_w[i];
        const float4* xr = (const float4*)(x + (size_t)cidx * C + lane * V);
        #pragma unroll
        for (int q = 0; q < V / 4; q++) {
            float4 xv = __ldg(&xr[q]);
            acc[q * 4 + 0] += wt * xv.x;
            acc[q * 4 + 1] += wt * xv.y;
            acc[q * 4 + 2] += wt * xv.z;
            acc[q * 4 + 3] += wt * xv.w;
        }
    }
    float4* orow = (float4*)(out + (size_t)warp * C + lane * V);
    #pragma unroll
    for (int q = 0; q < V / 4; q++)
        orow[q] = make_float4(acc[q * 4], acc[q * 4 + 1], acc[q * 4 + 2], acc[q * 4 + 3]);
}

// ---------------- GEMM: C[M_PAD,N] = relu(A[M_PAD,K] @ W[K,N] + b) ------------
#define BM 128
#define BN 128
#define BK 8
#define TM 8
#define TN 8

__global__ void __launch_bounds__(256)
gemm_bias_relu_kernel(const float* __restrict__ A, const float* __restrict__ W,
                      const float* __restrict__ bias, float* __restrict__ C,
                      int K, int N) {
    __shared__ float As[BK][BM];
    __shared__ float Bs[BK][BN];
    int tid = threadIdx.x;
    int tr = tid / (BN / TN);       // 0..15
    int tc = tid % (BN / TN);       // 0..15
    int aRow = tid >> 1;            // 0..127
    int aCol = (tid & 1) * 4;       // 0 or 4
    int bRow = tid >> 5;            // 0..7
    int bCol = (tid & 31) * 4;      // 0..124

    const float* Ablk = A + (size_t)(blockIdx.y * BM) * K;
    const float* Wblk = W + blockIdx.x * BN;

    float acc[TM][TN];
    #pragma unroll
    for (int i = 0; i < TM; i++)
        #pragma unroll
        for (int j = 0; j < TN; j++) acc[i][j] = 0.f;

    for (int k0 = 0; k0 < K; k0 += BK) {
        float4 a4 = *(const float4*)(Ablk + (size_t)aRow * K + k0 + aCol);
        As[aCol + 0][aRow] = a4.x;
        As[aCol + 1][aRow] = a4.y;
        As[aCol + 2][aRow] = a4.z;
        As[aCol + 3][aRow] = a4.w;
        float4 b4 = *(const float4*)(Wblk + (size_t)(k0 + bRow) * N + bCol);
        *(float4*)&Bs[bRow][bCol] = b4;
        __syncthreads();
        #pragma unroll
        for (int k = 0; k < BK; k++) {
            float ar[TM], br[TN];
            #pragma unroll
            for (int i = 0; i < TM; i++) ar[i] = As[k][tr * TM + i];
            #pragma unroll
            for (int j = 0; j < TN; j++) br[j] = Bs[k][tc * TN + j];
            #pragma unroll
            for (int i = 0; i < TM; i++)
                #pragma unroll
                for (int j = 0; j < TN; j++) acc[i][j] += ar[i] * br[j];
        }
        __syncthreads();
    }

    #pragma unroll
    for (int i = 0; i < TM; i++) {
        size_t row = (size_t)blockIdx.y * BM + tr * TM + i;
        #pragma unroll
        for (int j = 0; j < TN; j += 4) {
            int col = blockIdx.x * BN + tc * TN + j;
            float4 o;
            o.x = fmaxf(acc[i][j + 0] + bias[col + 0], 0.f);
            o.y = fmaxf(acc[i][j + 1] + bias[col + 1], 0.f);
            o.z = fmaxf(acc[i][j + 2] + bias[col + 2], 0.f);
            o.w = fmaxf(acc[i][j + 3] + bias[col + 3], 0.f);
            *(float4*)(C + row * N + col) = o;
        }
    }
}

// ---------------- pooling ------------------------------------------------------
__global__ void graph_ranges_kernel(const int* __restrict__ batch) {
    int g = blockIdx.x * blockDim.x + threadIdx.x;
    if (g > N_GRAPHS) return;
    int lo = 0, hi = N_NODES;
    while (lo < hi) {
        int mid = (lo + hi) >> 1;
        if (batch[mid] < g) lo = mid + 1; else hi = mid;
    }
    g_gstart[g] = lo;
}

__global__ void pool_kernel(const float* __restrict__ h, float* __restrict__ out) {
    int g = blockIdx.x;
    int c = threadIdx.x;                  // 256 channels
    int s = g_gstart[g], e = g_gstart[g + 1];
    float acc = 0.f;
    for (int v = s; v < e; v++) acc += h[(size_t)v * HID + c];
    out[(size_t)g * HID + c] = acc;
}

// ---------------- launch -------------------------------------------------------
extern "C" void kernel_launch(void* const* d_in, const int* in_sizes, int n_in,
                              void* d_out, int out_size) {
    const float* x   = (const float*)d_in[0];   // [50000,128]
    const float* W0  = (const float*)d_in[1];   // [128,256]
    const float* b0  = (const float*)d_in[2];   // [256]
    const float* W1  = (const float*)d_in[3];   // [256,256]
    const float* b1  = (const float*)d_in[4];
    const float* W2  = (const float*)d_in[5];
    const float* b2  = (const float*)d_in[6];
    const int*   ei  = (const int*)d_in[7];     // [2,800000]
    const int*   bat = (const int*)d_in[8];     // [50000]
    float* out = (float*)d_out;

    const int* src = ei;
    const int* dst = ei + N_EDGES;

    float* bufA; cudaGetSymbolAddress((void**)&bufA, g_bufA);
    float* bufB; cudaGetSymbolAddress((void**)&bufB, g_bufB);
    float* bufC; cudaGetSymbolAddress((void**)&bufC, g_bufC);

    // --- normalization + CSR (layer-independent) ---
    init_deg_kernel<<<(N_NODES + 255) / 256, 256>>>();
    count_kernel<<<(N_EDGES + 255) / 256, 256>>>(dst);
    dinv_kernel<<<(N_NODES + 255) / 256, 256>>>();
    scan_kernel<<<1, 1024>>>();
    place_edges_kernel<<<(N_EDGES + 255) / 256, 256>>>(src, dst);
    place_loops_kernel<<<(N_NODES + 255) / 256, 256>>>();
    zero_pads_kernel<<<(48 * HID + 255) / 256, 256>>>();

    dim3 gemm_grid(HID / BN, M_PAD / BM);   // (2, 391)
    int agg_blocks = (N_NODES * 32 + 255) / 256;

    // layer 0: agg(x) -> bufA [50000,128]; gemm K=128 -> bufB
    aggregate_kernel<IN_CH><<<agg_blocks, 256>>>(x, bufA);
    gemm_bias_relu_kernel<<<gemm_grid, 256>>>(bufA, W0, b0, bufB, IN_CH, HID);

    // layer 1: agg(bufB) -> bufC; gemm K=256 -> bufB
    aggregate_kernel<HID><<<agg_blocks, 256>>>(bufB, bufC);
    gemm_bias_relu_kernel<<<gemm_grid, 256>>>(bufC, W1, b1, bufB, HID, HID);

    // layer 2
    aggregate_kernel<HID><<<agg_blocks, 256>>>(bufB, bufC);
    gemm_bias_relu_kernel<<<gemm_grid, 256>>>(bufC, W2, b2, bufB, HID, HID);

    // pool
    graph_ranges_kernel<<<3, 256>>>(bat);
    pool_kernel<<<N_GRAPHS, HID>>>(bufB, out);
}

// round 6
// speedup vs baseline: 1.2467x; 1.2467x over previous
#include <cuda_runtime.h>
#include <cstdint>

// Problem constants
#define N_NODES   50000
#define N_EDGES   800000
#define N_TOT     850000      // edges + self loops
#define IN_CH     128
#define HID       256
#define N_GRAPHS  512
#define M_PAD     50048       // 391 * 128
#define SCAN_NB   196         // ceil(50000/256)

// ---------------- scratch (device globals; no allocation allowed) -------------
__device__ float g_bufA[(size_t)M_PAD * IN_CH];
__device__ float g_bufB[(size_t)M_PAD * HID];
__device__ float g_bufC[(size_t)M_PAD * HID];
__device__ int   g_deg[N_NODES];
__device__ float g_dinv[N_NODES];
__device__ int   g_rowptr[N_NODES + 1];
__device__ int   g_cursor[N_NODES];
__device__ int   g_col[N_TOT];
__device__ float g_w[N_TOT];
__device__ int   g_gstart[N_GRAPHS + 1];
__device__ int   g_psum[SCAN_NB + 4];
__device__ int   g_poff[SCAN_NB + 4];

// ---------------- preprocessing ----------------------------------------------
__global__ void init_deg_kernel() {
    int i = blockIdx.x * blockDim.x + threadIdx.x;
    if (i < N_NODES) g_deg[i] = 1;   // self loop
}

__global__ void count_kernel(const int* __restrict__ dst) {
    int e = blockIdx.x * blockDim.x + threadIdx.x;
    if (e < N_EDGES) atomicAdd(&g_deg[dst[e]], 1);
}

__global__ void dinv_kernel() {
    int i = blockIdx.x * blockDim.x + threadIdx.x;
    if (i < N_NODES) g_dinv[i] = rsqrtf((float)g_deg[i]);
}

// ---- 3-phase scan: block sums -> scan partials -> per-block scan + offset ----
__global__ void block_sum_kernel() {               // grid SCAN_NB, 256 thr
    int b = blockIdx.x, t = threadIdx.x;
    int idx = b * 256 + t;
    int v = (idx < N_NODES) ? g_deg[idx] : 0;
    #pragma unroll
    for (int off = 16; off > 0; off >>= 1)
        v += __shfl_down_sync(0xffffffffu, v, off);
    __shared__ int ws[8];
    if ((t & 31) == 0) ws[t >> 5] = v;
    __syncthreads();
    if (t == 0) {
        int s = 0;
        #pragma unroll
        for (int i = 0; i < 8; i++) s += ws[i];
        g_psum[b] = s;
    }
}

__global__ void scan_partials_kernel() {           // 1 block, 256 thr
    int t = threadIdx.x, lane = t & 31, w = t >> 5;
    int v = (t < SCAN_NB) ? g_psum[t] : 0;
    int x = v;
    #pragma unroll
    for (int off = 1; off < 32; off <<= 1) {
        int y = __shfl_up_sync(0xffffffffu, x, off);
        if (lane >= off) x += y;
    }
    __shared__ int wsum[8];
    if (lane == 31) wsum[w] = x;
    __syncthreads();
    if (t == 0) {
        int run = 0;
        #pragma unroll
        for (int i = 0; i < 8; i++) { int tmp = wsum[i]; wsum[i] = run; run += tmp; }
    }
    __syncthreads();
    g_poff[t] = x + wsum[w] - v;                   // exclusive prefix
}

__global__ void scan_write_kernel() {              // grid SCAN_NB, 256 thr
    int b = blockIdx.x, t = threadIdx.x, lane = t & 31, w = t >> 5;
    int idx = b * 256 + t;
    int v = (idx < N_NODES) ? g_deg[idx] : 0;
    int x = v;
    #pragma unroll
    for (int off = 1; off < 32; off <<= 1) {
        int y = __shfl_up_sync(0xffffffffu, x, off);
        if (lane >= off) x += y;
    }
    __shared__ int wsum[8];
    if (lane == 31) wsum[w] = x;
    __syncthreads();
    if (t == 0) {
        int run = 0;
        #pragma unroll
        for (int i = 0; i < 8; i++) { int tmp = wsum[i]; wsum[i] = run; run += tmp; }
    }
    __syncthreads();
    int excl = g_poff[b] + x + wsum[w] - v;
    if (idx < N_NODES) { g_rowptr[idx] = excl; g_cursor[idx] = excl; }
    if (b == 0 && t == 0) g_rowptr[N_NODES] = N_TOT;
}

__global__ void place_edges_kernel(const int* __restrict__ src,
                                   const int* __restrict__ dst) {
    int e = blockIdx.x * blockDim.x + threadIdx.x;
    if (e >= N_EDGES) return;
    int s = src[e], d = dst[e];
    int pos = atomicAdd(&g_cursor[d], 1);
    g_col[pos] = s;
    g_w[pos]   = g_dinv[s] * g_dinv[d];
}

__global__ void place_loops_kernel() {
    int v = blockIdx.x * blockDim.x + threadIdx.x;
    if (v >= N_NODES) return;
    int pos = atomicAdd(&g_cursor[v], 1);
    g_col[pos] = v;
    float dv = g_dinv[v];
    g_w[pos]  = dv * dv;
}

__global__ void zero_pads_kernel() {
    int i = blockIdx.x * blockDim.x + threadIdx.x;
    const int PAD = M_PAD - N_NODES;            // 48
    if (i < PAD * IN_CH) g_bufA[(size_t)N_NODES * IN_CH + i] = 0.f;
    if (i < PAD * HID) {
        g_bufB[(size_t)N_NODES * HID + i] = 0.f;
        g_bufC[(size_t)N_NODES * HID + i] = 0.f;
    }
}

// ---------------- aggregation: out[v] = sum_e w[e] * x[col[e]] ----------------
template <int C>
__global__ void __launch_bounds__(256)
aggregate_kernel(const float* __restrict__ x, float* __restrict__ out) {
    int warp = (blockIdx.x * blockDim.x + threadIdx.x) >> 5;
    int lane = threadIdx.x & 31;
    if (warp >= N_NODES) return;
    constexpr int V = C / 32;                   // floats per lane (4 or 8)
    float acc[V];
    #pragma unroll
    for (int q = 0; q < V; q++) acc[q] = 0.f;
    int s = g_rowptr[warp], e = g_rowptr[warp + 1];
    int i = s;
    // unroll-by-4: 4 independent row gathers in flight for MLP
    for (; i + 4 <= e; i += 4) {
        int   c0 = g_col[i],   c1 = g_col[i+1], c2 = g_col[i+2], c3 = g_col[i+3];
        float w0 = g_w[i],     w1 = g_w[i+1],   w2 = g_w[i+2],   w3 = g_w[i+3];
        const float4* r0 = (const float4*)(x + (size_t)c0 * C + lane * V);
        const float4* r1 = (const float4*)(x + (size_t)c1 * C + lane * V);
        const float4* r2 = (const float4*)(x + (size_t)c2 * C + lane * V);
        const float4* r3 = (const float4*)(x + (size_t)c3 * C + lane * V);
        #pragma unroll
        for (int q = 0; q < V / 4; q++) {
            float4 v0 = __ldg(&r0[q]);
            float4 v1 = __ldg(&r1[q]);
            float4 v2 = __ldg(&r2[q]);
            float4 v3 = __ldg(&r3[q]);
            acc[q*4+0] += w0*v0.x; acc[q*4+1] += w0*v0.y; acc[q*4+2] += w0*v0.z; acc[q*4+3] += w0*v0.w;
            acc[q*4+0] += w1*v1.x; acc[q*4+1] += w1*v1.y; acc[q*4+2] += w1*v1.z; acc[q*4+3] += w1*v1.w;
            acc[q*4+0] += w2*v2.x; acc[q*4+1] += w2*v2.y; acc[q*4+2] += w2*v2.z; acc[q*4+3] += w2*v2.w;
            acc[q*4+0] += w3*v3.x; acc[q*4+1] += w3*v3.y; acc[q*4+2] += w3*v3.z; acc[q*4+3] += w3*v3.w;
        }
    }
    for (; i < e; i++) {
        int cidx = g_col[i];
        float wt = g_w[i];
        const float4* xr = (const float4*)(x + (size_t)cidx * C + lane * V);
        #pragma unroll
        for (int q = 0; q < V / 4; q++) {
            float4 xv = __ldg(&xr[q]);
            acc[q*4+0] += wt*xv.x; acc[q*4+1] += wt*xv.y; acc[q*4+2] += wt*xv.z; acc[q*4+3] += wt*xv.w;
        }
    }
    float4* orow = (float4*)(out + (size_t)warp * C + lane * V);
    #pragma unroll
    for (int q = 0; q < V / 4; q++)
        orow[q] = make_float4(acc[q*4], acc[q*4+1], acc[q*4+2], acc[q*4+3]);
}

// ---------------- GEMM: 3xTF32 tensor-core, C = relu(A@W + b) ------------------
#define BM 128
#define BN 128
#define BKT 16
#define SMP (BM + 4)   // padded stride

__device__ __forceinline__ void tf32_split(float v, float& hi, float& lo) {
    uint32_t h;
    asm("cvt.rna.tf32.f32 %0, %1;" : "=r"(h) : "f"(v));
    hi = __uint_as_float(h);
    float r = v - hi;
    uint32_t l;
    asm("cvt.rna.tf32.f32 %0, %1;" : "=r"(l) : "f"(r));
    lo = __uint_as_float(l);
}

#define MMA_TF32(d, a, b)                                                     \
    asm volatile(                                                             \
        "mma.sync.aligned.m16n8k8.row.col.f32.tf32.tf32.f32 "                 \
        "{%0,%1,%2,%3}, {%4,%5,%6,%7}, {%8,%9}, {%0,%1,%2,%3};"               \
        : "+f"((d)[0]), "+f"((d)[1]), "+f"((d)[2]), "+f"((d)[3])              \
        : "r"(__float_as_uint((a)[0])), "r"(__float_as_uint((a)[1])),         \
          "r"(__float_as_uint((a)[2])), "r"(__float_as_uint((a)[3])),         \
          "r"(__float_as_uint((b)[0])), "r"(__float_as_uint((b)[1])))

__global__ void __launch_bounds__(256)
gemm_tf32_bias_relu(const float* __restrict__ A, const float* __restrict__ W,
                    const float* __restrict__ bias, float* __restrict__ C,
                    int K, int N) {
    __shared__ float As_hi[BKT][SMP], As_lo[BKT][SMP];
    __shared__ float Bs_hi[BKT][SMP], Bs_lo[BKT][SMP];
    int tid = threadIdx.x, lane = tid & 31, wid = tid >> 5;
    int wm = (wid >> 2) * 64;            // 0 or 64
    int wn = (wid & 3) * 32;             // 0..96

    float acc[4][4][4];
    #pragma unroll
    for (int i = 0; i < 4; i++)
        #pragma unroll
        for (int j = 0; j < 4; j++)
            #pragma unroll
            for (int q = 0; q < 4; q++) acc[i][j][q] = 0.f;

    const float* Ablk = A + (size_t)blockIdx.y * BM * K;
    const float* Wblk = W + blockIdx.x * BN;

    int ar = tid >> 1;                   // 0..127
    int ac = (tid & 1) * 8;              // 0 or 8
    int br = tid >> 4;                   // 0..15
    int bc = (tid & 15) * 8;             // 0..120

    int kq = lane & 3;                   // k within fragment
    int rq = lane >> 2;                  // row/col within fragment

    for (int k0 = 0; k0 < K; k0 += BKT) {
        // ---- load + split A tile (128x16), store transposed [k][m] ----
        float4 av0 = *(const float4*)(Ablk + (size_t)ar * K + k0 + ac);
        float4 av1 = *(const float4*)(Ablk + (size_t)ar * K + k0 + ac + 4);
        {
            float hi, lo;
            tf32_split(av0.x, hi, lo); As_hi[ac+0][ar] = hi; As_lo[ac+0][ar] = lo;
            tf32_split(av0.y, hi, lo); As_hi[ac+1][ar] = hi; As_lo[ac+1][ar] = lo;
            tf32_split(av0.z, hi, lo); As_hi[ac+2][ar] = hi; As_lo[ac+2][ar] = lo;
            tf32_split(av0.w, hi, lo); As_hi[ac+3][ar] = hi; As_lo[ac+3][ar] = lo;
            tf32_split(av1.x, hi, lo); As_hi[ac+4][ar] = hi; As_lo[ac+4][ar] = lo;
            tf32_split(av1.y, hi, lo); As_hi[ac+5][ar] = hi; As_lo[ac+5][ar] = lo;
            tf32_split(av1.z, hi, lo); As_hi[ac+6][ar] = hi; As_lo[ac+6][ar] = lo;
            tf32_split(av1.w, hi, lo); As_hi[ac+7][ar] = hi; As_lo[ac+7][ar] = lo;
        }
        // ---- load + split B tile (16x128), store [k][n] ----
        float4 bv0 = *(const float4*)(Wblk + (size_t)(k0 + br) * N + bc);
        float4 bv1 = *(const float4*)(Wblk + (size_t)(k0 + br) * N + bc + 4);
        {
            float4 h0, l0, h1, l1;
            tf32_split(bv0.x, h0.x, l0.x); tf32_split(bv0.y, h0.y, l0.y);
            tf32_split(bv0.z, h0.z, l0.z); tf32_split(bv0.w, h0.w, l0.w);
            tf32_split(bv1.x, h1.x, l1.x); tf32_split(bv1.y, h1.y, l1.y);
            tf32_split(bv1.z, h1.z, l1.z); tf32_split(bv1.w, h1.w, l1.w);
            *(float4*)&Bs_hi[br][bc]     = h0;
            *(float4*)&Bs_hi[br][bc + 4] = h1;
            *(float4*)&Bs_lo[br][bc]     = l0;
            *(float4*)&Bs_lo[br][bc + 4] = l1;
        }
        __syncthreads();

        #pragma unroll
        for (int kk = 0; kk < BKT; kk += 8) {
            int kA = kk + kq;
            float ah[4][4], al[4][4];
            #pragma unroll
            for (int mt = 0; mt < 4; mt++) {
                int r0 = wm + mt * 16 + rq;
                ah[mt][0] = As_hi[kA    ][r0];     ah[mt][1] = As_hi[kA    ][r0 + 8];
                ah[mt][2] = As_hi[kA + 4][r0];     ah[mt][3] = As_hi[kA + 4][r0 + 8];
                al[mt][0] = As_lo[kA    ][r0];     al[mt][1] = As_lo[kA    ][r0 + 8];
                al[mt][2] = As_lo[kA + 4][r0];     al[mt][3] = As_lo[kA + 4][r0 + 8];
            }
            float bh[4][2], bl[4][2];
            #pragma unroll
            for (int nt = 0; nt < 4; nt++) {
                int n = wn + nt * 8 + rq;
                bh[nt][0] = Bs_hi[kA    ][n];
                bh[nt][1] = Bs_hi[kA + 4][n];
                bl[nt][0] = Bs_lo[kA    ][n];
                bl[nt][1] = Bs_lo[kA + 4][n];
            }
            #pragma unroll
            for (int mt = 0; mt < 4; mt++)
                #pragma unroll
                for (int nt = 0; nt < 4; nt++) {
                    MMA_TF32(acc[mt][nt], ah[mt], bh[nt]);
                    MMA_TF32(acc[mt][nt], ah[mt], bl[nt]);
                    MMA_TF32(acc[mt][nt], al[mt], bh[nt]);
                }
        }
        __syncthreads();
    }

    // ---- epilogue: bias + relu, float2 stores ----
    #pragma unroll
    for (int mt = 0; mt < 4; mt++) {
        int row0 = blockIdx.y * BM + wm + mt * 16 + rq;
        #pragma unroll
        for (int nt = 0; nt < 4; nt++) {
            int col = blockIdx.x * BN + wn + nt * 8 + (lane & 3) * 2;
            float2 bb = *(const float2*)(bias + col);
            float2 o0, o1;
            o0.x = fmaxf(acc[mt][nt][0] + bb.x, 0.f);
            o0.y = fmaxf(acc[mt][nt][1] + bb.y, 0.f);
            o1.x = fmaxf(acc[mt][nt][2] + bb.x, 0.f);
            o1.y = fmaxf(acc[mt][nt][3] + bb.y, 0.f);
            *(float2*)(C + (size_t)row0 * N + col)       = o0;
            *(float2*)(C + (size_t)(row0 + 8) * N + col) = o1;
        }
    }
}

// ---------------- pooling ------------------------------------------------------
__global__ void graph_ranges_kernel(const int* __restrict__ batch) {
    int g = blockIdx.x * blockDim.x + threadIdx.x;
    if (g > N_GRAPHS) return;
    int lo = 0, hi = N_NODES;
    while (lo < hi) {
        int mid = (lo + hi) >> 1;
        if (batch[mid] < g) lo = mid + 1; else hi = mid;
    }
    g_gstart[g] = lo;
}

__global__ void pool_kernel(const float* __restrict__ h, float* __restrict__ out) {
    int g = blockIdx.x;
    int c = threadIdx.x;                  // 256 channels
    int s = g_gstart[g], e = g_gstart[g + 1];
    float acc = 0.f;
    int v = s;
    for (; v + 2 <= e; v += 2)
        acc += h[(size_t)v * HID + c] + h[(size_t)(v + 1) * HID + c];
    if (v < e) acc += h[(size_t)v * HID + c];
    out[(size_t)g * HID + c] = acc;
}

// ---------------- launch -------------------------------------------------------
extern "C" void kernel_launch(void* const* d_in, const int* in_sizes, int n_in,
                              void* d_out, int out_size) {
    const float* x   = (const float*)d_in[0];
    const float* W0  = (const float*)d_in[1];
    const float* b0  = (const float*)d_in[2];
    const float* W1  = (const float*)d_in[3];
    const float* b1  = (const float*)d_in[4];
    const float* W2  = (const float*)d_in[5];
    const float* b2  = (const float*)d_in[6];
    const int*   ei  = (const int*)d_in[7];
    const int*   bat = (const int*)d_in[8];
    float* out = (float*)d_out;

    const int* src = ei;
    const int* dst = ei + N_EDGES;

    float* bufA; cudaGetSymbolAddress((void**)&bufA, g_bufA);
    float* bufB; cudaGetSymbolAddress((void**)&bufB, g_bufB);
    float* bufC; cudaGetSymbolAddress((void**)&bufC, g_bufC);

    // --- normalization + CSR ---
    init_deg_kernel<<<(N_NODES + 255) / 256, 256>>>();
    count_kernel<<<(N_EDGES + 255) / 256, 256>>>(dst);
    dinv_kernel<<<(N_NODES + 255) / 256, 256>>>();
    block_sum_kernel<<<SCAN_NB, 256>>>();
    scan_partials_kernel<<<1, 256>>>();
    scan_write_kernel<<<SCAN_NB, 256>>>();
    place_edges_kernel<<<(N_EDGES + 255) / 256, 256>>>(src, dst);
    place_loops_kernel<<<(N_NODES + 255) / 256, 256>>>();
    zero_pads_kernel<<<(48 * HID + 255) / 256, 256>>>();

    dim3 gemm_grid(HID / BN, M_PAD / BM);   // (2, 391)
    int agg_blocks = (N_NODES * 32 + 255) / 256;

    // layer 0
    aggregate_kernel<IN_CH><<<agg_blocks, 256>>>(x, bufA);
    gemm_tf32_bias_relu<<<gemm_grid, 256>>>(bufA, W0, b0, bufB, IN_CH, HID);
    // layer 1
    aggregate_kernel<HID><<<agg_blocks, 256>>>(bufB, bufC);
    gemm_tf32_bias_relu<<<gemm_grid, 256>>>(bufC, W1, b1, bufB, HID, HID);
    // layer 2
    aggregate_kernel<HID><<<agg_blocks, 256>>>(bufB, bufC);
    gemm_tf32_bias_relu<<<gemm_grid, 256>>>(bufC, W2, b2, bufB, HID, HID);

    // pool
    graph_ranges_kernel<<<3, 256>>>(bat);
    pool_kernel<<<N_GRAPHS, HID>>>(bufB, out);
}

// round 7
// speedup vs baseline: 2.7181x; 2.1803x over previous
#include <cuda_runtime.h>
#include <cuda_fp16.h>
#include <cstdint>

// Problem constants
#define N_NODES   50000
#define N_EDGES   800000
#define N_TOT     850000      // edges + self loops
#define IN_CH     128
#define HID       256
#define N_GRAPHS  512
#define M_PAD     50048       // 391 * 128
#define SCAN_NB   196         // ceil(50000/256)

// ---------------- scratch (device globals; no allocation allowed) -------------
__device__ __half g_xh[(size_t)N_NODES * IN_CH];   // x in fp16
__device__ __half g_hA[(size_t)M_PAD * IN_CH];     // aggregated input
__device__ __half g_hB[(size_t)M_PAD * HID];       // gemm outputs
__device__ __half g_hC[(size_t)M_PAD * HID];       // aggregated hidden
__device__ __half g_w0t[HID * IN_CH];              // W0^T [256][128] fp16
__device__ __half g_w1t[HID * HID];                // W1^T
__device__ __half g_w2t[HID * HID];                // W2^T
__device__ int   g_deg[N_NODES];
__device__ float g_dinv[N_NODES];
__device__ int   g_rowptr[N_NODES + 1];
__device__ int   g_cursor[N_NODES];
__device__ int   g_col[N_TOT];
__device__ float g_w[N_TOT];
__device__ int   g_gstart[N_GRAPHS + 1];
__device__ int   g_psum[SCAN_NB + 4];
__device__ int   g_poff[SCAN_NB + 4];

// ---------------- preprocessing ----------------------------------------------
__global__ void init_deg_kernel() {
    int i = blockIdx.x * blockDim.x + threadIdx.x;
    if (i < N_NODES) g_deg[i] = 1;   // self loop
}

__global__ void count_kernel(const int* __restrict__ dst) {
    int e = blockIdx.x * blockDim.x + threadIdx.x;
    if (e < N_EDGES) atomicAdd(&g_deg[dst[e]], 1);
}

__global__ void dinv_kernel() {
    int i = blockIdx.x * blockDim.x + threadIdx.x;
    if (i < N_NODES) g_dinv[i] = rsqrtf((float)g_deg[i]);
}

// ---- 3-phase scan ----
__global__ void block_sum_kernel() {
    int b = blockIdx.x, t = threadIdx.x;
    int idx = b * 256 + t;
    int v = (idx < N_NODES) ? g_deg[idx] : 0;
    #pragma unroll
    for (int off = 16; off > 0; off >>= 1)
        v += __shfl_down_sync(0xffffffffu, v, off);
    __shared__ int ws[8];
    if ((t & 31) == 0) ws[t >> 5] = v;
    __syncthreads();
    if (t == 0) {
        int s = 0;
        #pragma unroll
        for (int i = 0; i < 8; i++) s += ws[i];
        g_psum[b] = s;
    }
}

__global__ void scan_partials_kernel() {
    int t = threadIdx.x, lane = t & 31, w = t >> 5;
    int v = (t < SCAN_NB) ? g_psum[t] : 0;
    int x = v;
    #pragma unroll
    for (int off = 1; off < 32; off <<= 1) {
        int y = __shfl_up_sync(0xffffffffu, x, off);
        if (lane >= off) x += y;
    }
    __shared__ int wsum[8];
    if (lane == 31) wsum[w] = x;
    __syncthreads();
    if (t == 0) {
        int run = 0;
        #pragma unroll
        for (int i = 0; i < 8; i++) { int tmp = wsum[i]; wsum[i] = run; run += tmp; }
    }
    __syncthreads();
    g_poff[t] = x + wsum[w] - v;
}

__global__ void scan_write_kernel() {
    int b = blockIdx.x, t = threadIdx.x, lane = t & 31, w = t >> 5;
    int idx = b * 256 + t;
    int v = (idx < N_NODES) ? g_deg[idx] : 0;
    int x = v;
    #pragma unroll
    for (int off = 1; off < 32; off <<= 1) {
        int y = __shfl_up_sync(0xffffffffu, x, off);
        if (lane >= off) x += y;
    }
    __shared__ int wsum[8];
    if (lane == 31) wsum[w] = x;
    __syncthreads();
    if (t == 0) {
        int run = 0;
        #pragma unroll
        for (int i = 0; i < 8; i++) { int tmp = wsum[i]; wsum[i] = run; run += tmp; }
    }
    __syncthreads();
    int excl = g_poff[b] + x + wsum[w] - v;
    if (idx < N_NODES) { g_rowptr[idx] = excl; g_cursor[idx] = excl; }
    if (b == 0 && t == 0) g_rowptr[N_NODES] = N_TOT;
}

__global__ void place_edges_kernel(const int* __restrict__ src,
                                   const int* __restrict__ dst) {
    int e = blockIdx.x * blockDim.x + threadIdx.x;
    if (e >= N_EDGES) return;
    int s = src[e], d = dst[e];
    int pos = atomicAdd(&g_cursor[d], 1);
    g_col[pos] = s;
    g_w[pos]   = g_dinv[s] * g_dinv[d];
}

__global__ void place_loops_kernel() {
    int v = blockIdx.x * blockDim.x + threadIdx.x;
    if (v >= N_NODES) return;
    int pos = atomicAdd(&g_cursor[v], 1);
    g_col[pos] = v;
    float dv = g_dinv[v];
    g_w[pos]  = dv * dv;
}

// ---------------- fp16 conversions --------------------------------------------
__global__ void conv_x_kernel(const float* __restrict__ x) {
    int i = blockIdx.x * blockDim.x + threadIdx.x;   // over float4 chunks
    const int NC4 = N_NODES * IN_CH / 4;
    if (i >= NC4) return;
    float4 v = *(const float4*)(x + (size_t)i * 4);
    __half2 h0 = __float22half2_rn(make_float2(v.x, v.y));
    __half2 h1 = __float22half2_rn(make_float2(v.z, v.w));
    *(uint2*)(&g_xh[(size_t)i * 4]) = make_uint2(
        *(const unsigned*)&h0, *(const unsigned*)&h1);
}

__global__ void conv_w_kernel(const float* __restrict__ W, __half* __restrict__ Wt,
                              int K, int N) {
    int i = blockIdx.x * blockDim.x + threadIdx.x;   // over K*N
    if (i >= K * N) return;
    int n = i / K, k = i % K;                        // Wt[n][k] = W[k][n]
    Wt[i] = __float2half(W[(size_t)k * N + n]);
}

__global__ void zero_pads_kernel() {
    int i = blockIdx.x * blockDim.x + threadIdx.x;
    const int PAD = M_PAD - N_NODES;                 // 48
    if (i < PAD * IN_CH) g_hA[(size_t)N_NODES * IN_CH + i] = __float2half(0.f);
    if (i < PAD * HID) {
        g_hB[(size_t)N_NODES * HID + i] = __float2half(0.f);
        g_hC[(size_t)N_NODES * HID + i] = __float2half(0.f);
    }
}

// ---------------- aggregation (fp16 in/out, fp32 accum) ------------------------
template <int C>
__global__ void __launch_bounds__(256)
aggregate_h_kernel(const __half* __restrict__ x, __half* __restrict__ out) {
    int warp = (blockIdx.x * blockDim.x + threadIdx.x) >> 5;
    int lane = threadIdx.x & 31;
    if (warp >= N_NODES) return;
    constexpr int V = C / 32;                        // halfs per lane: 4 or 8
    float acc[V];
    #pragma unroll
    for (int q = 0; q < V; q++) acc[q] = 0.f;
    int s = g_rowptr[warp], e = g_rowptr[warp + 1];

    auto accum = [&](int cidx, float wt) {
        const __half* p = x + (size_t)cidx * C + lane * V;
        if constexpr (V == 4) {
            uint2 u = __ldg((const uint2*)p);
            __half2 h0 = *(__half2*)&u.x, h1 = *(__half2*)&u.y;
            float2 f0 = __half22float2(h0), f1 = __half22float2(h1);
            acc[0] += wt * f0.x; acc[1] += wt * f0.y;
            acc[2] += wt * f1.x; acc[3] += wt * f1.y;
        } else {
            uint4 u = __ldg((const uint4*)p);
            __half2 h0 = *(__half2*)&u.x, h1 = *(__half2*)&u.y;
            __half2 h2 = *(__half2*)&u.z, h3 = *(__half2*)&u.w;
            float2 f0 = __half22float2(h0), f1 = __half22float2(h1);
            float2 f2 = __half22float2(h2), f3 = __half22float2(h3);
            acc[0] += wt * f0.x; acc[1] += wt * f0.y;
            acc[2] += wt * f1.x; acc[3] += wt * f1.y;
            acc[4] += wt * f2.x; acc[5] += wt * f2.y;
            acc[6] += wt * f3.x; acc[7] += wt * f3.y;
        }
    };

    int i = s;
    for (; i + 4 <= e; i += 4) {
        int   c0 = g_col[i],   c1 = g_col[i+1], c2 = g_col[i+2], c3 = g_col[i+3];
        float w0 = g_w[i],     w1 = g_w[i+1],   w2 = g_w[i+2],   w3 = g_w[i+3];
        accum(c0, w0); accum(c1, w1); accum(c2, w2); accum(c3, w3);
    }
    for (; i < e; i++) accum(g_col[i], g_w[i]);

    __half* orow = out + (size_t)warp * C + lane * V;
    if constexpr (V == 4) {
        __half2 o0 = __float22half2_rn(make_float2(acc[0], acc[1]));
        __half2 o1 = __float22half2_rn(make_float2(acc[2], acc[3]));
        *(uint2*)orow = make_uint2(*(unsigned*)&o0, *(unsigned*)&o1);
    } else {
        __half2 o0 = __float22half2_rn(make_float2(acc[0], acc[1]));
        __half2 o1 = __float22half2_rn(make_float2(acc[2], acc[3]));
        __half2 o2 = __float22half2_rn(make_float2(acc[4], acc[5]));
        __half2 o3 = __float22half2_rn(make_float2(acc[6], acc[7]));
        *(uint4*)orow = make_uint4(*(unsigned*)&o0, *(unsigned*)&o1,
                                   *(unsigned*)&o2, *(unsigned*)&o3);
    }
}

// ---------------- GEMM: fp16 MMA (m16n8k16), fp32 accum, bias+relu -> fp16 -----
#define BM 128
#define BN 128
#define BKH 32
#define HSTR 40   // half stride (80 B, 16B-aligned, conflict-free fragment LDS)

#define MMA_F16(d, a0, a1, a2, a3, b0, b1)                                    \
    asm volatile(                                                             \
        "mma.sync.aligned.m16n8k16.row.col.f32.f16.f16.f32 "                  \
        "{%0,%1,%2,%3}, {%4,%5,%6,%7}, {%8,%9}, {%0,%1,%2,%3};"               \
        : "+f"((d)[0]), "+f"((d)[1]), "+f"((d)[2]), "+f"((d)[3])              \
        : "r"(a0), "r"(a1), "r"(a2), "r"(a3), "r"(b0), "r"(b1))

__global__ void __launch_bounds__(256)
gemm_f16_bias_relu(const __half* __restrict__ A, const __half* __restrict__ Wt,
                   const float* __restrict__ bias, __half* __restrict__ C,
                   int K, int N) {
    __shared__ __align__(16) __half As[BM][HSTR];   // [m][k]
    __shared__ __align__(16) __half Bs[BN][HSTR];   // [n][k]
    int tid = threadIdx.x, lane = tid & 31, wid = tid >> 5;
    int wm = (wid >> 2) * 64;            // 0 or 64
    int wn = (wid & 3) * 32;             // 0..96
    int g = lane >> 2;                   // 0..7
    int t = lane & 3;                    // 0..3

    float acc[4][4][4];
    #pragma unroll
    for (int i = 0; i < 4; i++)
        #pragma unroll
        for (int j = 0; j < 4; j++)
            #pragma unroll
            for (int q = 0; q < 4; q++) acc[i][j][q] = 0.f;

    const __half* Ablk = A + (size_t)blockIdx.y * BM * K;
    const __half* Wblk = Wt + (size_t)blockIdx.x * BN * K;

    int ldr = tid >> 1;                  // 0..127
    int ldc = (tid & 1) * 16;            // 0 or 16 (halfs)

    for (int k0 = 0; k0 < K; k0 += BKH) {
        // A tile: 128x32 halfs, 32B per thread
        const __half* ap = Ablk + (size_t)ldr * K + k0 + ldc;
        uint4 av0 = *(const uint4*)ap;
        uint4 av1 = *(const uint4*)(ap + 8);
        *(uint4*)&As[ldr][ldc]     = av0;
        *(uint4*)&As[ldr][ldc + 8] = av1;
        // B tile: 128x32 halfs from Wt[n][k]
        const __half* bp = Wblk + (size_t)ldr * K + k0 + ldc;
        uint4 bv0 = *(const uint4*)bp;
        uint4 bv1 = *(const uint4*)(bp + 8);
        *(uint4*)&Bs[ldr][ldc]     = bv0;
        *(uint4*)&Bs[ldr][ldc + 8] = bv1;
        __syncthreads();

        #pragma unroll
        for (int kk = 0; kk < BKH; kk += 16) {
            int kbase = kk + 2 * t;
            uint a0[4], a1[4], a2[4], a3[4];
            #pragma unroll
            for (int mt = 0; mt < 4; mt++) {
                int r = wm + mt * 16 + g;
                a0[mt] = *(const uint*)&As[r    ][kbase];
                a1[mt] = *(const uint*)&As[r + 8][kbase];
                a2[mt] = *(const uint*)&As[r    ][kbase + 8];
                a3[mt] = *(const uint*)&As[r + 8][kbase + 8];
            }
            uint b0[4], b1[4];
            #pragma unroll
            for (int nt = 0; nt < 4; nt++) {
                int n = wn + nt * 8 + g;
                b0[nt] = *(const uint*)&Bs[n][kbase];
                b1[nt] = *(const uint*)&Bs[n][kbase + 8];
            }
            #pragma unroll
            for (int mt = 0; mt < 4; mt++)
                #pragma unroll
                for (int nt = 0; nt < 4; nt++)
                    MMA_F16(acc[mt][nt], a0[mt], a1[mt], a2[mt], a3[mt],
                            b0[nt], b1[nt]);
        }
        __syncthreads();
    }

    // epilogue: bias + relu, fp16 stores (half2)
    #pragma unroll
    for (int mt = 0; mt < 4; mt++) {
        int row0 = blockIdx.y * BM + wm + mt * 16 + g;
        #pragma unroll
        for (int nt = 0; nt < 4; nt++) {
            int col = blockIdx.x * BN + wn + nt * 8 + 2 * t;
            float2 bb = *(const float2*)(bias + col);
            __half2 o0 = __float22half2_rn(make_float2(
                fmaxf(acc[mt][nt][0] + bb.x, 0.f),
                fmaxf(acc[mt][nt][1] + bb.y, 0.f)));
            __half2 o1 = __float22half2_rn(make_float2(
                fmaxf(acc[mt][nt][2] + bb.x, 0.f),
                fmaxf(acc[mt][nt][3] + bb.y, 0.f)));
            *(unsigned*)(C + (size_t)row0 * N + col)       = *(unsigned*)&o0;
            *(unsigned*)(C + (size_t)(row0 + 8) * N + col) = *(unsigned*)&o1;
        }
    }
}

// ---------------- pooling ------------------------------------------------------
__global__ void graph_ranges_kernel(const int* __restrict__ batch) {
    int gph = blockIdx.x * blockDim.x + threadIdx.x;
    if (gph > N_GRAPHS) return;
    int lo = 0, hi = N_NODES;
    while (lo < hi) {
        int mid = (lo + hi) >> 1;
        if (batch[mid] < gph) lo = mid + 1; else hi = mid;
    }
    g_gstart[gph] = lo;
}

__global__ void pool_kernel(const __half* __restrict__ h, float* __restrict__ out) {
    int gph = blockIdx.x;
    int c = threadIdx.x;                  // 256 channels
    int s = g_gstart[gph], e = g_gstart[gph + 1];
    float acc = 0.f;
    int v = s;
    for (; v + 2 <= e; v += 2)
        acc += __half2float(h[(size_t)v * HID + c]) +
               __half2float(h[(size_t)(v + 1) * HID + c]);
    if (v < e) acc += __half2float(h[(size_t)v * HID + c]);
    out[(size_t)gph * HID + c] = acc;
}

// ---------------- launch -------------------------------------------------------
extern "C" void kernel_launch(void* const* d_in, const int* in_sizes, int n_in,
                              void* d_out, int out_size) {
    const float* x   = (const float*)d_in[0];
    const float* W0  = (const float*)d_in[1];
    const float* b0  = (const float*)d_in[2];
    const float* W1  = (const float*)d_in[3];
    const float* b1  = (const float*)d_in[4];
    const float* W2  = (const float*)d_in[5];
    const float* b2  = (const float*)d_in[6];
    const int*   ei  = (const int*)d_in[7];
    const int*   bat = (const int*)d_in[8];
    float* out = (float*)d_out;

    const int* src = ei;
    const int* dst = ei + N_EDGES;

    __half* xh;  cudaGetSymbolAddress((void**)&xh,  g_xh);
    __half* hA;  cudaGetSymbolAddress((void**)&hA,  g_hA);
    __half* hB;  cudaGetSymbolAddress((void**)&hB,  g_hB);
    __half* hC;  cudaGetSymbolAddress((void**)&hC,  g_hC);
    __half* w0t; cudaGetSymbolAddress((void**)&w0t, g_w0t);
    __half* w1t; cudaGetSymbolAddress((void**)&w1t, g_w1t);
    __half* w2t; cudaGetSymbolAddress((void**)&w2t, g_w2t);

    // --- normalization + CSR ---
    init_deg_kernel<<<(N_NODES + 255) / 256, 256>>>();
    count_kernel<<<(N_EDGES + 255) / 256, 256>>>(dst);
    dinv_kernel<<<(N_NODES + 255) / 256, 256>>>();
    block_sum_kernel<<<SCAN_NB, 256>>>();
    scan_partials_kernel<<<1, 256>>>();
    scan_write_kernel<<<SCAN_NB, 256>>>();
    place_edges_kernel<<<(N_EDGES + 255) / 256, 256>>>(src, dst);
    place_loops_kernel<<<(N_NODES + 255) / 256, 256>>>();

    // --- fp16 conversions ---
    conv_x_kernel<<<(N_NODES * IN_CH / 4 + 255) / 256, 256>>>(x);
    conv_w_kernel<<<(IN_CH * HID + 255) / 256, 256>>>(W0, w0t, IN_CH, HID);
    conv_w_kernel<<<(HID * HID + 255) / 256, 256>>>(W1, w1t, HID, HID);
    conv_w_kernel<<<(HID * HID + 255) / 256, 256>>>(W2, w2t, HID, HID);
    zero_pads_kernel<<<(48 * HID + 255) / 256, 256>>>();

    dim3 gemm_grid(HID / BN, M_PAD / BM);   // (2, 391)
    int agg_blocks = (N_NODES * 32 + 255) / 256;

    // layer 0
    aggregate_h_kernel<IN_CH><<<agg_blocks, 256>>>(xh, hA);
    gemm_f16_bias_relu<<<gemm_grid, 256>>>(hA, w0t, b0, hB, IN_CH, HID);
    // layer 1
    aggregate_h_kernel<HID><<<agg_blocks, 256>>>(hB, hC);
    gemm_f16_bias_relu<<<gemm_grid, 256>>>(hC, w1t, b1, hB, HID, HID);
    // layer 2
    aggregate_h_kernel<HID><<<agg_blocks, 256>>>(hB, hC);
    gemm_f16_bias_relu<<<gemm_grid, 256>>>(hC, w2t, b2, hB, HID, HID);

    // pool
    graph_ranges_kernel<<<3, 256>>>(bat);
    pool_kernel<<<N_GRAPHS, HID>>>(hB, out);
}

// round 8
// speedup vs baseline: 3.1046x; 1.1422x over previous
#include <cuda_runtime.h>
#include <cuda_fp16.h>
#include <cstdint>

// Problem constants
#define N_NODES   50000
#define N_EDGES   800000
#define N_TOT     850000      // edges + self loops
#define IN_CH     128
#define HID       256
#define N_GRAPHS  512
#define M_PAD     50048       // 391 * 128
#define SCAN_NB   196         // ceil(50000/256)
#define NC4       (N_NODES * IN_CH / 4)   // 1,600,000 float4 chunks of x

// ---------------- scratch (device globals; no allocation allowed) -------------
__device__ __half g_xh[(size_t)N_NODES * IN_CH];   // x in fp16
__device__ __half g_hA[(size_t)M_PAD * IN_CH];     // aggregated input
__device__ __half g_hB[(size_t)M_PAD * HID];       // gemm outputs
__device__ __half g_hC[(size_t)M_PAD * HID];       // aggregated hidden
__device__ __half g_w0t[HID * IN_CH];              // W0^T [256][128] fp16
__device__ __half g_w1t[HID * HID];                // W1^T
__device__ __half g_w2t[HID * HID];                // W2^T
__device__ int   g_deg[N_NODES];
__device__ float g_dinv[N_NODES];
__device__ int   g_rowptr[N_NODES + 1];
__device__ int   g_cursor[N_NODES];
__device__ int   g_col[N_TOT];
__device__ float g_w[N_TOT];
__device__ int   g_gstart[N_GRAPHS + 1];
__device__ int   g_psum[SCAN_NB + 4];

// ---------------- fused elementwise setup --------------------------------------
// conv_x + W0/W1/W2 transpose-to-fp16 + pad zeroing + deg init + graph ranges.
__global__ void setup_kernel(const float* __restrict__ x,
                             const float* __restrict__ W0,
                             const float* __restrict__ W1,
                             const float* __restrict__ W2,
                             const int* __restrict__ batch) {
    int i = blockIdx.x * blockDim.x + threadIdx.x;
    if (i < NC4) {
        float4 v = *(const float4*)(x + (size_t)i * 4);
        __half2 h0 = __float22half2_rn(make_float2(v.x, v.y));
        __half2 h1 = __float22half2_rn(make_float2(v.z, v.w));
        *(uint2*)(&g_xh[(size_t)i * 4]) = make_uint2(
            *(const unsigned*)&h0, *(const unsigned*)&h1);
    }
    if (i < N_NODES) g_deg[i] = 1;                      // self loop
    if (i < HID * IN_CH) {                              // W0^T
        int n = i / IN_CH, k = i % IN_CH;
        g_w0t[i] = __float2half(W0[(size_t)k * HID + n]);
    }
    if (i < HID * HID) {                                // W1^T, W2^T
        int n = i / HID, k = i % HID;
        g_w1t[i] = __float2half(W1[(size_t)k * HID + n]);
        g_w2t[i] = __float2half(W2[(size_t)k * HID + n]);
    }
    if (i < (M_PAD - N_NODES) * IN_CH)
        g_hA[(size_t)N_NODES * IN_CH + i] = __float2half(0.f);
    if (i < (M_PAD - N_NODES) * HID) {
        g_hB[(size_t)N_NODES * HID + i] = __float2half(0.f);
        g_hC[(size_t)N_NODES * HID + i] = __float2half(0.f);
    }
    if (i <= N_GRAPHS) {                                // graph ranges
        int lo = 0, hi = N_NODES;
        while (lo < hi) {
            int mid = (lo + hi) >> 1;
            if (batch[mid] < i) lo = mid + 1; else hi = mid;
        }
        g_gstart[i] = lo;
    }
}

__global__ void count_kernel(const int* __restrict__ dst) {
    int e = blockIdx.x * blockDim.x + threadIdx.x;
    if (e < N_EDGES) atomicAdd(&g_deg[dst[e]], 1);
}

// block sums for scan + dinv (elementwise, deg is final here)
__global__ void bsum_dinv_kernel() {
    int b = blockIdx.x, t = threadIdx.x;
    int idx = b * 256 + t;
    int d = (idx < N_NODES) ? g_deg[idx] : 0;
    if (idx < N_NODES) g_dinv[idx] = rsqrtf((float)d);
    int v = d;
    #pragma unroll
    for (int off = 16; off > 0; off >>= 1)
        v += __shfl_down_sync(0xffffffffu, v, off);
    __shared__ int ws[8];
    if ((t & 31) == 0) ws[t >> 5] = v;
    __syncthreads();
    if (t == 0) {
        int s = 0;
        #pragma unroll
        for (int i = 0; i < 8; i++) s += ws[i];
        g_psum[b] = s;
    }
}

// per-block scan; block offset computed inline by summing partials < b
__global__ void scan_write_kernel() {
    int b = blockIdx.x, t = threadIdx.x, lane = t & 31, w = t >> 5;
    // ---- block offset = sum_{j<b} g_psum[j]  (b <= 195 < 256) ----
    int contrib = (t < b) ? g_psum[t] : 0;
    #pragma unroll
    for (int off = 16; off > 0; off >>= 1)
        contrib += __shfl_down_sync(0xffffffffu, contrib, off);
    __shared__ int rs[8];
    __shared__ int off_s;
    if ((t & 31) == 0) rs[t >> 5] = contrib;
    __syncthreads();
    if (t == 0) {
        int s = 0;
        #pragma unroll
        for (int i = 0; i < 8; i++) s += rs[i];
        off_s = s;
    }
    // ---- per-element scan ----
    int idx = b * 256 + t;
    int v = (idx < N_NODES) ? g_deg[idx] : 0;
    int x = v;
    #pragma unroll
    for (int off = 1; off < 32; off <<= 1) {
        int y = __shfl_up_sync(0xffffffffu, x, off);
        if (lane >= off) x += y;
    }
    __shared__ int wsum[8];
    if (lane == 31) wsum[w] = x;
    __syncthreads();
    if (t == 0) {
        int run = 0;
        #pragma unroll
        for (int i = 0; i < 8; i++) { int tmp = wsum[i]; wsum[i] = run; run += tmp; }
    }
    __syncthreads();
    int excl = off_s + x + wsum[w] - v;
    if (idx < N_NODES) { g_rowptr[idx] = excl; g_cursor[idx] = excl; }
    if (b == 0 && t == 0) g_rowptr[N_NODES] = N_TOT;
}

// edges + self loops in one launch
__global__ void place_all_kernel(const int* __restrict__ src,
                                 const int* __restrict__ dst) {
    int e = blockIdx.x * blockDim.x + threadIdx.x;
    if (e < N_EDGES) {
        int s = src[e], d = dst[e];
        int pos = atomicAdd(&g_cursor[d], 1);
        g_col[pos] = s;
        g_w[pos]   = g_dinv[s] * g_dinv[d];
    } else {
        int v = e - N_EDGES;
        if (v < N_NODES) {
            int pos = atomicAdd(&g_cursor[v], 1);
            g_col[pos] = v;
            float dv = g_dinv[v];
            g_w[pos]  = dv * dv;
        }
    }
}

// ---------------- aggregation (fp16 in/out, fp32 accum) ------------------------
template <int C>
__global__ void __launch_bounds__(256)
aggregate_h_kernel(const __half* __restrict__ x, __half* __restrict__ out) {
    int warp = (blockIdx.x * blockDim.x + threadIdx.x) >> 5;
    int lane = threadIdx.x & 31;
    if (warp >= N_NODES) return;
    constexpr int V = C / 32;                        // halfs per lane: 4 or 8
    float acc[V];
    #pragma unroll
    for (int q = 0; q < V; q++) acc[q] = 0.f;
    int s = g_rowptr[warp], e = g_rowptr[warp + 1];

    auto accum = [&](int cidx, float wt) {
        const __half* p = x + (size_t)cidx * C + lane * V;
        if constexpr (V == 4) {
            uint2 u = __ldg((const uint2*)p);
            __half2 h0 = *(__half2*)&u.x, h1 = *(__half2*)&u.y;
            float2 f0 = __half22float2(h0), f1 = __half22float2(h1);
            acc[0] += wt * f0.x; acc[1] += wt * f0.y;
            acc[2] += wt * f1.x; acc[3] += wt * f1.y;
        } else {
            uint4 u = __ldg((const uint4*)p);
            __half2 h0 = *(__half2*)&u.x, h1 = *(__half2*)&u.y;
            __half2 h2 = *(__half2*)&u.z, h3 = *(__half2*)&u.w;
            float2 f0 = __half22float2(h0), f1 = __half22float2(h1);
            float2 f2 = __half22float2(h2), f3 = __half22float2(h3);
            acc[0] += wt * f0.x; acc[1] += wt * f0.y;
            acc[2] += wt * f1.x; acc[3] += wt * f1.y;
            acc[4] += wt * f2.x; acc[5] += wt * f2.y;
            acc[6] += wt * f3.x; acc[7] += wt * f3.y;
        }
    };

    int i = s;
    for (; i + 4 <= e; i += 4) {
        int   c0 = g_col[i],   c1 = g_col[i+1], c2 = g_col[i+2], c3 = g_col[i+3];
        float w0 = g_w[i],     w1 = g_w[i+1],   w2 = g_w[i+2],   w3 = g_w[i+3];
        accum(c0, w0); accum(c1, w1); accum(c2, w2); accum(c3, w3);
    }
    for (; i < e; i++) accum(g_col[i], g_w[i]);

    __half* orow = out + (size_t)warp * C + lane * V;
    if constexpr (V == 4) {
        __half2 o0 = __float22half2_rn(make_float2(acc[0], acc[1]));
        __half2 o1 = __float22half2_rn(make_float2(acc[2], acc[3]));
        *(uint2*)orow = make_uint2(*(unsigned*)&o0, *(unsigned*)&o1);
    } else {
        __half2 o0 = __float22half2_rn(make_float2(acc[0], acc[1]));
        __half2 o1 = __float22half2_rn(make_float2(acc[2], acc[3]));
        __half2 o2 = __float22half2_rn(make_float2(acc[4], acc[5]));
        __half2 o3 = __float22half2_rn(make_float2(acc[6], acc[7]));
        *(uint4*)orow = make_uint4(*(unsigned*)&o0, *(unsigned*)&o1,
                                   *(unsigned*)&o2, *(unsigned*)&o3);
    }
}

// ---------------- GEMM: fp16 MMA, cp.async double-buffered ---------------------
#define BM 128
#define BN 128
#define BKH 32
#define HSTR 40   // half stride (80 B, 16B-aligned, conflict-free fragment LDS)

#define MMA_F16(d, a0, a1, a2, a3, b0, b1)                                    \
    asm volatile(                                                             \
        "mma.sync.aligned.m16n8k16.row.col.f32.f16.f16.f32 "                  \
        "{%0,%1,%2,%3}, {%4,%5,%6,%7}, {%8,%9}, {%0,%1,%2,%3};"               \
        : "+f"((d)[0]), "+f"((d)[1]), "+f"((d)[2]), "+f"((d)[3])              \
        : "r"(a0), "r"(a1), "r"(a2), "r"(a3), "r"(b0), "r"(b1))

__device__ __forceinline__ void cpa16(void* sm, const void* gm) {
    uint32_t sa = (uint32_t)__cvta_generic_to_shared(sm);
    asm volatile("cp.async.cg.shared.global [%0], [%1], 16;" :: "r"(sa), "l"(gm));
}

__global__ void __launch_bounds__(256)
gemm_f16_bias_relu(const __half* __restrict__ A, const __half* __restrict__ Wt,
                   const float* __restrict__ bias, __half* __restrict__ C,
                   int K, int N) {
    __shared__ __align__(16) __half As[2][BM][HSTR];   // [stage][m][k]
    __shared__ __align__(16) __half Bs[2][BN][HSTR];   // [stage][n][k]
    int tid = threadIdx.x, lane = tid & 31, wid = tid >> 5;
    int wm = (wid >> 2) * 64;            // 0 or 64
    int wn = (wid & 3) * 32;             // 0..96
    int g = lane >> 2;                   // 0..7
    int t = lane & 3;                    // 0..3

    float acc[4][4][4];
    #pragma unroll
    for (int i = 0; i < 4; i++)
        #pragma unroll
        for (int j = 0; j < 4; j++)
            #pragma unroll
            for (int q = 0; q < 4; q++) acc[i][j][q] = 0.f;

    const __half* Ablk = A + (size_t)blockIdx.y * BM * K;
    const __half* Wblk = Wt + (size_t)blockIdx.x * BN * K;

    int ldr = tid >> 1;                  // 0..127
    int ldc = (tid & 1) * 16;            // 0 or 16 (halfs)

    int niter = K / BKH;

    auto issue = [&](int it) {
        int st = it & 1;
        int k0 = it * BKH;
        const __half* ap = Ablk + (size_t)ldr * K + k0 + ldc;
        cpa16(&As[st][ldr][ldc],     ap);
        cpa16(&As[st][ldr][ldc + 8], ap + 8);
        const __half* bp = Wblk + (size_t)ldr * K + k0 + ldc;
        cpa16(&Bs[st][ldr][ldc],     bp);
        cpa16(&Bs[st][ldr][ldc + 8], bp + 8);
        asm volatile("cp.async.commit_group;");
    };

    issue(0);
    for (int it = 0; it < niter; it++) {
        if (it + 1 < niter) {
            issue(it + 1);
            asm volatile("cp.async.wait_group 1;");
        } else {
            asm volatile("cp.async.wait_group 0;");
        }
        __syncthreads();
        int st = it & 1;
        #pragma unroll
        for (int kk = 0; kk < BKH; kk += 16) {
            int kbase = kk + 2 * t;
            uint a0[4], a1[4], a2[4], a3[4];
            #pragma unroll
            for (int mt = 0; mt < 4; mt++) {
                int r = wm + mt * 16 + g;
                a0[mt] = *(const uint*)&As[st][r    ][kbase];
                a1[mt] = *(const uint*)&As[st][r + 8][kbase];
                a2[mt] = *(const uint*)&As[st][r    ][kbase + 8];
                a3[mt] = *(const uint*)&As[st][r + 8][kbase + 8];
            }
            uint b0[4], b1[4];
            #pragma unroll
            for (int nt = 0; nt < 4; nt++) {
                int n = wn + nt * 8 + g;
                b0[nt] = *(const uint*)&Bs[st][n][kbase];
                b1[nt] = *(const uint*)&Bs[st][n][kbase + 8];
            }
            #pragma unroll
            for (int mt = 0; mt < 4; mt++)
                #pragma unroll
                for (int nt = 0; nt < 4; nt++)
                    MMA_F16(acc[mt][nt], a0[mt], a1[mt], a2[mt], a3[mt],
                            b0[nt], b1[nt]);
        }
        __syncthreads();
    }

    // epilogue: bias + relu, fp16 stores (half2)
    #pragma unroll
    for (int mt = 0; mt < 4; mt++) {
        int row0 = blockIdx.y * BM + wm + mt * 16 + g;
        #pragma unroll
        for (int nt = 0; nt < 4; nt++) {
            int col = blockIdx.x * BN + wn + nt * 8 + 2 * t;
            float2 bb = *(const float2*)(bias + col);
            __half2 o0 = __float22half2_rn(make_float2(
                fmaxf(acc[mt][nt][0] + bb.x, 0.f),
                fmaxf(acc[mt][nt][1] + bb.y, 0.f)));
            __half2 o1 = __float22half2_rn(make_float2(
                fmaxf(acc[mt][nt][2] + bb.x, 0.f),
                fmaxf(acc[mt][nt][3] + bb.y, 0.f)));
            *(unsigned*)(C + (size_t)row0 * N + col)       = *(unsigned*)&o0;
            *(unsigned*)(C + (size_t)(row0 + 8) * N + col) = *(unsigned*)&o1;
        }
    }
}

// ---------------- pooling ------------------------------------------------------
__global__ void pool_kernel(const __half* __restrict__ h, float* __restrict__ out) {
    int gph = blockIdx.x;
    int c = threadIdx.x;                  // 256 channels
    int s = g_gstart[gph], e = g_gstart[gph + 1];
    float acc = 0.f;
    int v = s;
    for (; v + 2 <= e; v += 2)
        acc += __half2float(h[(size_t)v * HID + c]) +
               __half2float(h[(size_t)(v + 1) * HID + c]);
    if (v < e) acc += __half2float(h[(size_t)v * HID + c]);
    out[(size_t)gph * HID + c] = acc;
}

// ---------------- launch -------------------------------------------------------
extern "C" void kernel_launch(void* const* d_in, const int* in_sizes, int n_in,
                              void* d_out, int out_size) {
    const float* x   = (const float*)d_in[0];
    const float* W0  = (const float*)d_in[1];
    const float* b0  = (const float*)d_in[2];
    const float* W1  = (const float*)d_in[3];
    const float* b1  = (const float*)d_in[4];
    const float* W2  = (const float*)d_in[5];
    const float* b2  = (const float*)d_in[6];
    const int*   ei  = (const int*)d_in[7];
    const int*   bat = (const int*)d_in[8];
    float* out = (float*)d_out;

    const int* src = ei;
    const int* dst = ei + N_EDGES;

    __half* xh;  cudaGetSymbolAddress((void**)&xh,  g_xh);
    __half* hA;  cudaGetSymbolAddress((void**)&hA,  g_hA);
    __half* hB;  cudaGetSymbolAddress((void**)&hB,  g_hB);
    __half* hC;  cudaGetSymbolAddress((void**)&hC,  g_hC);
    __half* w0t; cudaGetSymbolAddress((void**)&w0t, g_w0t);
    __half* w1t; cudaGetSymbolAddress((void**)&w1t, g_w1t);
    __half* w2t; cudaGetSymbolAddress((void**)&w2t, g_w2t);

    // prep: fused setup + CSR chain (7 -> 5 nodes)
    setup_kernel<<<(NC4 + 255) / 256, 256>>>(x, W0, W1, W2, bat);
    count_kernel<<<(N_EDGES + 255) / 256, 256>>>(dst);
    bsum_dinv_kernel<<<SCAN_NB, 256>>>();
    scan_write_kernel<<<SCAN_NB, 256>>>();
    place_all_kernel<<<(N_TOT + 255) / 256, 256>>>(src, dst);

    dim3 gemm_grid(HID / BN, M_PAD / BM);   // (2, 391)
    int agg_blocks = (N_NODES * 32 + 255) / 256;

    // layer 0
    aggregate_h_kernel<IN_CH><<<agg_blocks, 256>>>(xh, hA);
    gemm_f16_bias_relu<<<gemm_grid, 256>>>(hA, w0t, b0, hB, IN_CH, HID);
    // layer 1
    aggregate_h_kernel<HID><<<agg_blocks, 256>>>(hB, hC);
    gemm_f16_bias_relu<<<gemm_grid, 256>>>(hC, w1t, b1, hB, HID, HID);
    // layer 2
    aggregate_h_kernel<HID><<<agg_blocks, 256>>>(hB, hC);
    gemm_f16_bias_relu<<<gemm_grid, 256>>>(hC, w2t, b2, hB, HID, HID);

    // pool
    pool_kernel<<<N_GRAPHS, HID>>>(hB, out);
}